// round 8
// baseline (speedup 1.0000x reference)
#include <cuda_runtime.h>
#include <cuda_pipeline.h>

#define BB 16
#define HH 768
#define WW 768
#define KK 512
#define HWSZ (HH * WW)

#define TROWS 8                        // rows per tile
#define TILES_PER_IMG (HH / TROWS)     // 96
#define NTILES (BB * TILES_PER_IMG)    // 1536
#define NGT BB                         // 16 gt-correction blocks
#define NBULK 280                      // bulk blocks (total 296 = one wave at 2/SM)
#define NBLOCKS (NGT + NBULK)          // 296
#define BT 512                         // threads per block
#define F4_ROW (WW / 4)                // 192
#define TILE_F4 (TROWS * F4_ROW)       // 1536
#define PRE_FLOATS ((TROWS + 2) * WW)  // 7680
#define GT_FLOATS (TROWS * WW)         // 6144
#define STAGE_FLOATS (PRE_FLOATS + GT_FLOATS)   // 13824
#define SMEM_BYTES (2 * STAGE_FLOATS * 4)       // 110592
#define BM_WORDS (HWSZ / 32)           // 18432 words (73728 B <= SMEM_BYTES)

__device__ double g_acc[2];            // [0]=l1, [1]=l2 (zero at load; last block resets)
__device__ unsigned int g_done;

#define FULL 0xffffffffu

__inline__ __device__ float warp_reduce(float v) {
    #pragma unroll
    for (int o = 16; o > 0; o >>= 1) v += __shfl_down_sync(FULL, v, o);
    return v;
}

__device__ __forceinline__ void prefetch_tile(
    const float* __restrict__ pre, const float* __restrict__ gt,
    int tt, float* __restrict__ sp, float* __restrict__ sg, int tid)
{
    const int b  = tt / TILES_PER_IMG;
    const int y0 = (tt % TILES_PER_IMG) * TROWS;
    const int lo = (y0 == 0) ? 0 : y0 - 1;
    const int hi = (y0 + TROWS >= HH) ? HH - 1 : y0 + TROWS;
    const int nrows  = hi - lo + 1;          // 9 or 10
    const int dstrow = lo - (y0 - 1);        // 1 iff top tile else 0

    const float4 z4 = make_float4(0.f, 0.f, 0.f, 0.f);
    if (y0 == 0)
        for (int i = tid; i < F4_ROW; i += BT)
            reinterpret_cast<float4*>(sp)[i] = z4;
    if (y0 + TROWS >= HH)
        for (int i = tid; i < F4_ROW; i += BT)
            reinterpret_cast<float4*>(sp + (TROWS + 1) * WW)[i] = z4;

    const float* srcp = pre + b * HWSZ + lo * WW;
    float* dstp = sp + dstrow * WW;
    const int nch = nrows * F4_ROW;
    for (int i = tid; i < nch; i += BT)
        __pipeline_memcpy_async(dstp + i * 4, srcp + i * 4, 16);

    const float* srcg = gt + b * HWSZ + y0 * WW;
    for (int i = tid; i < TILE_F4; i += BT)
        __pipeline_memcpy_async(sg + i * 4, srcg + i * 4, 16);
}

__device__ __forceinline__ void compute_tile(
    const float* __restrict__ sp, const float* __restrict__ sg,
    int tid, float& s1, float& s2)
{
    #pragma unroll
    for (int k = 0; k < TILE_F4 / BT; k++) {
        const int f  = tid + k * BT;
        const int r  = f / F4_ROW;
        const int x0 = (f - r * F4_ROW) * 4;
        const int cb = (r + 1) * WW + x0;

        const float4 c = *reinterpret_cast<const float4*>(sp + cb);
        const float4 u = *reinterpret_cast<const float4*>(sp + cb - WW);
        const float4 d = *reinterpret_cast<const float4*>(sp + cb + WW);
        const float4 g = *reinterpret_cast<const float4*>(sg + r * WW + x0);
        const float lft = (x0 > 0)      ? sp[cb - 1] : 0.f;
        const float rgt = (x0 + 4 < WW) ? sp[cb + 4] : 0.f;

        const float cv[4] = {c.x, c.y, c.z, c.w};
        const float gv[4] = {g.x, g.y, g.z, g.w};
        const float uv[4] = {u.x, u.y, u.z, u.w};
        const float dv[4] = {d.x, d.y, d.z, d.w};
        const float lv[4] = {lft, c.x, c.y, c.z};
        const float rv[4] = {c.y, c.z, c.w, rgt};

        #pragma unroll
        for (int i = 0; i < 4; i++) {
            const float df  = cv[i] - gv[i];
            const float err = df * df;
            const float nb  = fmaxf(fmaxf(lv[i], rv[i]), fmaxf(uv[i], dv[i]));
            s1 += (cv[i] > nb) ? err : 0.f;
            s2  = fmaf((gv[i] > 0.f) ? 5.f : 1.f, err, s2);
        }
    }
}

__global__ void __launch_bounds__(BT) fused_kernel(
    const float* __restrict__ pre, const float* __restrict__ gt,
    const int* __restrict__ cors, float* __restrict__ out)
{
    extern __shared__ float smem[];
    const int tid = threadIdx.x;
    float s1 = 0.f, s2 = 0.f;

    if (blockIdx.x < NGT) {
        // ---- gt-point correction with O(K) bitmap dedup ----
        unsigned int* bm = reinterpret_cast<unsigned int*>(smem);
        for (int i = tid; i < BM_WORDS; i += BT) bm[i] = 0u;
        __syncthreads();

        const int b = blockIdx.x;
        if (tid < KK) {
            const int x = cors[(b * KK + tid) * 2 + 0];
            const int y = cors[(b * KK + tid) * 2 + 1];
            const int key = y * WW + x;
            const unsigned int bit = 1u << (key & 31);
            const unsigned int old = atomicOr(&bm[key >> 5], bit);
            if (!(old & bit)) {    // first occurrence of this cell
                const int base = b * HWSZ + key;
                const float cc = pre[base];
                const float l = (x > 0)      ? pre[base - 1]  : 0.f;
                const float r = (x < WW - 1) ? pre[base + 1]  : 0.f;
                const float u = (y > 0)      ? pre[base - WW] : 0.f;
                const float d = (y < HH - 1) ? pre[base + WW] : 0.f;
                const bool pm = (cc > l) && (cc > r) && (cc > u) && (cc > d);
                const float diff = cc - gt[base];
                s1 = (diff * diff) * (pm ? -1.f : 1.f);
            }
        }
    } else {
        // ---- bulk pass: cp.async double-buffered tile pipeline ----
        float* sp[2] = {smem,              smem + STAGE_FLOATS};
        float* sg[2] = {smem + PRE_FLOATS, smem + STAGE_FLOATS + PRE_FLOATS};

        const int bid = blockIdx.x - NGT;                 // 0..NBULK-1
        const int n   = (NTILES - bid + NBULK - 1) / NBULK;   // 5 or 6 tiles

        prefetch_tile(pre, gt, bid, sp[0], sg[0], tid);
        __pipeline_commit();

        for (int i = 0; i < n; i++) {
            if (i + 1 < n) {
                prefetch_tile(pre, gt, bid + (i + 1) * NBULK,
                              sp[(i + 1) & 1], sg[(i + 1) & 1], tid);
                __pipeline_commit();
                __pipeline_wait_prior(1);
            } else {
                __pipeline_wait_prior(0);
            }
            __syncthreads();
            compute_tile(sp[i & 1], sg[i & 1], tid, s1, s2);
            __syncthreads();
        }
    }

    // ---- Block reduction + two double atomics + last-block finalize ----
    __shared__ float sh1[BT / 32], sh2[BT / 32];
    const int lane = tid & 31, wid = tid >> 5;
    s1 = warp_reduce(s1);
    s2 = warp_reduce(s2);
    if (lane == 0) { sh1[wid] = s1; sh2[wid] = s2; }
    __syncthreads();

    if (tid < 32) {
        float v1 = (lane < BT / 32) ? sh1[lane] : 0.f;
        float v2 = (lane < BT / 32) ? sh2[lane] : 0.f;
        v1 = warp_reduce(v1);
        v2 = warp_reduce(v2);
        if (lane == 0) {
            atomicAdd(&g_acc[0], (double)v1);
            atomicAdd(&g_acc[1], (double)v2);
            __threadfence();
            const unsigned int done = atomicAdd(&g_done, 1u);
            if (done == NBLOCKS - 1) {
                // last block: all partials are in L2 (atomics are device-coherent)
                __threadfence();
                const double a0 = atomicAdd(&g_acc[0], 0.0);
                const double a1 = atomicAdd(&g_acc[1], 0.0);
                out[0] = (float)((a0 + a1) / (double)BB);
                g_acc[0] = 0.0;
                g_acc[1] = 0.0;
                g_done = 0u;
            }
        }
    }
}

extern "C" void kernel_launch(void* const* d_in, const int* in_sizes, int n_in,
                              void* d_out, int out_size)
{
    const float* pre  = (const float*)d_in[0];
    const float* gt   = (const float*)d_in[1];
    const int*   cors = (const int*)d_in[2];
    float*       out  = (float*)d_out;

    static bool attr_done = false;
    if (!attr_done) {
        cudaFuncSetAttribute(fused_kernel,
                             cudaFuncAttributeMaxDynamicSharedMemorySize, SMEM_BYTES);
        attr_done = true;
    }

    fused_kernel<<<NBLOCKS, BT, SMEM_BYTES>>>(pre, gt, cors, out);
}

// round 9
// speedup vs baseline: 1.1212x; 1.1212x over previous
#include <cuda_runtime.h>
#include <cuda_pipeline.h>

#define BB 16
#define HH 768
#define WW 768
#define KK 512
#define HWSZ (HH * WW)

#define TROWS 8                        // rows per tile
#define TILES_PER_IMG (HH / TROWS)     // 96
#define NTILES (BB * TILES_PER_IMG)    // 1536
#define NGT BB                         // 16 gt-correction blocks
#define NBULK 428                      // bulk blocks (total 444 = one wave at 3/SM)
#define NBLOCKS (NGT + NBULK)          // 444
#define BT 512                         // threads per block
#define F4_ROW (WW / 4)                // 192
#define TILE_F4 (TROWS * F4_ROW)       // 1536
#define PRE_FLOATS ((TROWS + 2) * WW)  // 7680 floats = 30720 B per stage
#define SMEM_BYTES (2 * PRE_FLOATS * 4)   // 61440 B -> 3 blocks/SM
#define BM_WORDS (HWSZ / 32)           // 18432 words per batch

__device__ double g_acc[2];            // zero at load; last block resets each launch
__device__ unsigned int g_done;
__device__ unsigned int g_bm[BB][BM_WORDS];   // zero at load; gt blocks re-clear touched words

#define FULL 0xffffffffu

__inline__ __device__ float warp_reduce(float v) {
    #pragma unroll
    for (int o = 16; o > 0; o >>= 1) v += __shfl_down_sync(FULL, v, o);
    return v;
}

// Stage only pre rows (with halo) into smem.
__device__ __forceinline__ void prefetch_tile(
    const float* __restrict__ pre, int tt, float* __restrict__ sp, int tid)
{
    const int b  = tt / TILES_PER_IMG;
    const int y0 = (tt % TILES_PER_IMG) * TROWS;
    const int lo = (y0 == 0) ? 0 : y0 - 1;
    const int hi = (y0 + TROWS >= HH) ? HH - 1 : y0 + TROWS;
    const int nrows  = hi - lo + 1;          // 9 or 10
    const int dstrow = lo - (y0 - 1);        // 1 iff top tile else 0

    const float4 z4 = make_float4(0.f, 0.f, 0.f, 0.f);
    if (y0 == 0)
        for (int i = tid; i < F4_ROW; i += BT)
            reinterpret_cast<float4*>(sp)[i] = z4;
    if (y0 + TROWS >= HH)
        for (int i = tid; i < F4_ROW; i += BT)
            reinterpret_cast<float4*>(sp + (TROWS + 1) * WW)[i] = z4;

    const float* srcp = pre + b * HWSZ + lo * WW;
    float* dstp = sp + dstrow * WW;
    const int nch = nrows * F4_ROW;
    for (int i = tid; i < nch; i += BT)
        __pipeline_memcpy_async(dstp + i * 4, srcp + i * 4, 16);
}

// Compute over a tile: pre from smem, gt straight from global (no reuse).
__device__ __forceinline__ void compute_tile(
    const float* __restrict__ sp, const float* __restrict__ gtile,
    int tid, float& s1, float& s2)
{
    #pragma unroll
    for (int k = 0; k < TILE_F4 / BT; k++) {
        const int f  = tid + k * BT;
        const int r  = f / F4_ROW;
        const int x0 = (f - r * F4_ROW) * 4;
        const int cb = (r + 1) * WW + x0;

        const float4 g = *reinterpret_cast<const float4*>(gtile + r * WW + x0);
        const float4 c = *reinterpret_cast<const float4*>(sp + cb);
        const float4 u = *reinterpret_cast<const float4*>(sp + cb - WW);
        const float4 d = *reinterpret_cast<const float4*>(sp + cb + WW);
        const float lft = (x0 > 0)      ? sp[cb - 1] : 0.f;
        const float rgt = (x0 + 4 < WW) ? sp[cb + 4] : 0.f;

        const float cv[4] = {c.x, c.y, c.z, c.w};
        const float gv[4] = {g.x, g.y, g.z, g.w};
        const float uv[4] = {u.x, u.y, u.z, u.w};
        const float dv[4] = {d.x, d.y, d.z, d.w};
        const float lv[4] = {lft, c.x, c.y, c.z};
        const float rv[4] = {c.y, c.z, c.w, rgt};

        #pragma unroll
        for (int i = 0; i < 4; i++) {
            const float df  = cv[i] - gv[i];
            const float err = df * df;
            const float nb  = fmaxf(fmaxf(lv[i], rv[i]), fmaxf(uv[i], dv[i]));
            s1 += (cv[i] > nb) ? err : 0.f;
            s2  = fmaf((gv[i] > 0.f) ? 5.f : 1.f, err, s2);
        }
    }
}

__global__ void __launch_bounds__(BT) fused_kernel(
    const float* __restrict__ pre, const float* __restrict__ gt,
    const int* __restrict__ cors, float* __restrict__ out)
{
    extern __shared__ float smem[];
    const int tid = threadIdx.x;
    float s1 = 0.f, s2 = 0.f;

    if (blockIdx.x < NGT) {
        // ---- gt-point correction, dedup via persistent global bitmap ----
        const int b = blockIdx.x;
        unsigned int* bm = g_bm[b];
        int mykey = -1;

        if (tid < KK) {
            const int x = cors[(b * KK + tid) * 2 + 0];
            const int y = cors[(b * KK + tid) * 2 + 1];
            const int key = y * WW + x;
            mykey = key;
            const unsigned int bit = 1u << (key & 31);
            const unsigned int old = atomicOr(&bm[key >> 5], bit);
            if (!(old & bit)) {    // first occurrence of this cell
                const int base = b * HWSZ + key;
                const float cc = pre[base];
                const float l = (x > 0)      ? pre[base - 1]  : 0.f;
                const float r = (x < WW - 1) ? pre[base + 1]  : 0.f;
                const float u = (y > 0)      ? pre[base - WW] : 0.f;
                const float d = (y < HH - 1) ? pre[base + WW] : 0.f;
                const bool pm = (cc > l) && (cc > r) && (cc > u) && (cc > d);
                const float diff = cc - gt[base];
                s1 = (diff * diff) * (pm ? -1.f : 1.f);
            }
        }
        __syncthreads();
        // Re-clear touched words so the bitmap is all-zero for the next replay.
        if (mykey >= 0) bm[mykey >> 5] = 0u;
    } else {
        // ---- bulk pass: cp.async double-buffered pre tiles; gt direct LDG ----
        float* sp[2] = {smem, smem + PRE_FLOATS};

        const int bid = blockIdx.x - NGT;                     // 0..NBULK-1
        const int n   = (NTILES - bid + NBULK - 1) / NBULK;   // 3 or 4 tiles

        prefetch_tile(pre, bid, sp[0], tid);
        __pipeline_commit();

        for (int i = 0; i < n; i++) {
            const int tt = bid + i * NBULK;
            if (i + 1 < n) {
                prefetch_tile(pre, bid + (i + 1) * NBULK, sp[(i + 1) & 1], tid);
                __pipeline_commit();
                __pipeline_wait_prior(1);
            } else {
                __pipeline_wait_prior(0);
            }
            __syncthreads();
            const int b  = tt / TILES_PER_IMG;
            const int y0 = (tt % TILES_PER_IMG) * TROWS;
            compute_tile(sp[i & 1], gt + b * HWSZ + y0 * WW, tid, s1, s2);
            __syncthreads();
        }
    }

    // ---- Block reduction + two double atomics + last-block finalize ----
    __shared__ float sh1[BT / 32], sh2[BT / 32];
    const int lane = tid & 31, wid = tid >> 5;
    s1 = warp_reduce(s1);
    s2 = warp_reduce(s2);
    if (lane == 0) { sh1[wid] = s1; sh2[wid] = s2; }
    __syncthreads();

    if (tid < 32) {
        float v1 = (lane < BT / 32) ? sh1[lane] : 0.f;
        float v2 = (lane < BT / 32) ? sh2[lane] : 0.f;
        v1 = warp_reduce(v1);
        v2 = warp_reduce(v2);
        if (lane == 0) {
            atomicAdd(&g_acc[0], (double)v1);
            atomicAdd(&g_acc[1], (double)v2);
            __threadfence();
            const unsigned int done = atomicAdd(&g_done, 1u);
            if (done == NBLOCKS - 1) {
                __threadfence();
                const double a0 = atomicAdd(&g_acc[0], 0.0);
                const double a1 = atomicAdd(&g_acc[1], 0.0);
                out[0] = (float)((a0 + a1) / (double)BB);
                g_acc[0] = 0.0;
                g_acc[1] = 0.0;
                g_done = 0u;
            }
        }
    }
}

extern "C" void kernel_launch(void* const* d_in, const int* in_sizes, int n_in,
                              void* d_out, int out_size)
{
    const float* pre  = (const float*)d_in[0];
    const float* gt   = (const float*)d_in[1];
    const int*   cors = (const int*)d_in[2];
    float*       out  = (float*)d_out;

    static bool attr_done = false;
    if (!attr_done) {
        cudaFuncSetAttribute(fused_kernel,
                             cudaFuncAttributeMaxDynamicSharedMemorySize, SMEM_BYTES);
        attr_done = true;
    }

    fused_kernel<<<NBLOCKS, BT, SMEM_BYTES>>>(pre, gt, cors, out);
}